// round 5
// baseline (speedup 1.0000x reference)
#include <cuda_runtime.h>
#include <cuda_bf16.h>
#include <math.h>

// ---------------- constants ----------------
#define B_ 16
#define N_ 4096
#define C_ 256
#define H_ 4
#define D_ 64
#define M_ (B_ * N_)              // 65536
#define OUT_MAIN (M_ * C_)        // 16777216
#define OUT_S (B_ * H_ * D_ * D_) // 262144

typedef unsigned int u32;
typedef unsigned long long u64;

// ---------------- device scratch ----------------
__device__ __nv_bfloat16 g_qh[M_ * C_], g_ql[M_ * C_];
__device__ __nv_bfloat16 g_kh[M_ * C_], g_kl[M_ * C_];
__device__ float g_v[M_ * C_];
__device__ float g_y[M_ * C_];
__device__ __nv_bfloat16 g_wsh[4][C_ * C_], g_wsl[4][C_ * C_]; // q,k,v,o
__device__ float g_beta[B_ * H_ * N_];
__device__ float g_ss[M_ * H_];
__device__ float g_invrms[M_];
__device__ float g_perr[64 * 64 * 64], g_pkey[64 * 64 * 64];
__device__ float g_werr[64 * 64], g_wkey[64 * 64];

// ---------------- helpers ----------------
__device__ __forceinline__ u32 smem_u32(const void* p) {
    u32 a;
    asm("{ .reg .u64 t; cvta.to.shared.u64 t, %1; cvt.u32.u64 %0, t; }" : "=r"(a) : "l"(p));
    return a;
}
__device__ __forceinline__ void ldmx4(u32* r, u32 addr) {
    asm volatile("ldmatrix.sync.aligned.m8n8.x4.shared.b16 {%0,%1,%2,%3}, [%4];"
                 : "=r"(r[0]), "=r"(r[1]), "=r"(r[2]), "=r"(r[3]) : "r"(addr));
}
__device__ __forceinline__ void mma_bf16(float* d, const u32* a, u32 b0, u32 b1) {
    asm volatile("mma.sync.aligned.m16n8k16.row.col.f32.bf16.bf16.f32 "
                 "{%0,%1,%2,%3}, {%4,%5,%6,%7}, {%8,%9}, {%0,%1,%2,%3};"
                 : "+f"(d[0]), "+f"(d[1]), "+f"(d[2]), "+f"(d[3])
                 : "r"(a[0]), "r"(a[1]), "r"(a[2]), "r"(a[3]), "r"(b0), "r"(b1));
}
__device__ __forceinline__ u32 pack2(float a, float b, float& ra, float& rb) {
    __nv_bfloat16 h0 = __float2bfloat16(a), h1 = __float2bfloat16(b);
    ra = a - __bfloat162float(h0);
    rb = b - __bfloat162float(h1);
    return (u32)__bfloat16_as_ushort(h0) | ((u32)__bfloat16_as_ushort(h1) << 16);
}
__device__ __forceinline__ float eluf(float v) {
    return (v > 0.f) ? (v + 1.f) : expf(v);
}

// ---------------- K0: weights -> split bf16 ----------------
__global__ void __launch_bounds__(256) convw_kernel(
    const float* __restrict__ Wq, const float* __restrict__ Wk,
    const float* __restrict__ Wv, const float* __restrict__ Wo)
{
    int gid = blockIdx.x * 256 + threadIdx.x;   // < 262144
    int sel = gid >> 16, idx = gid & 65535;
    const float* W = (sel == 0) ? Wq : (sel == 1) ? Wk : (sel == 2) ? Wv : Wo;
    float v = W[idx];
    __nv_bfloat16 h = __float2bfloat16(v);
    g_wsh[sel][idx] = h;
    g_wsl[sel][idx] = __float2bfloat16(v - __bfloat162float(h));
}

// ---------------- K1/K7: split-bf16 GEMM from fp32 A, 128x128 tiles, K=256 ----------------
// task 0: QKV from x (grid 6 x 512) + fused beta on bx==0
// task 1: out proj from g_y with fused rmsnorm scaling (grid 2 x 512)
__global__ void __launch_bounds__(256, 2)
gemm_mma_kernel(int task, const float* __restrict__ Xfp,
                const float* __restrict__ Wb, const float* __restrict__ grms,
                float* __restrict__ fout)
{
    extern __shared__ char smem[];
    __shared__ float s_g[1024];   // wb (task0) or grms (task1)
    const u32 sb = smem_u32(smem);
    const int tid = threadIdx.x, wid = tid >> 5, lane = tid & 31;
    const int m0 = blockIdx.y * 128;

    // device-side source selection (passing __device__ globals from host is invalid)
    const float* Afp = (task == 0) ? Xfp : g_y;

    int mode, n0;
    const __nv_bfloat16 *Bh, *Bl;
    bool doBeta = false;
    if (task == 0) {
        int wsel = blockIdx.x >> 1; mode = wsel; n0 = (blockIdx.x & 1) * 128;
        Bh = g_wsh[wsel]; Bl = g_wsl[wsel];
        doBeta = (blockIdx.x == 0);
        if (doBeta) for (int i = tid; i < 1024; i += 256) s_g[i] = Wb[i];
    } else {
        mode = 3; n0 = blockIdx.x * 128;
        Bh = g_wsh[3]; Bl = g_wsl[3];
        if (tid < 256) s_g[tid] = grms[tid];
    }
    __syncthreads();

    const u32 OAH = 0, OAL = 16384, OBH = 32768, OBL = 49152;
    const int wm = wid & 3, wn = wid >> 2;
    const int rA = (lane & 7) + ((lane >> 3) & 1) * 8, cAx = (lane >> 4) & 1;
    const int rB = (lane & 7) + ((lane >> 4) & 1) * 8, cBx = (lane >> 3) & 1;

    float acc[2][8][4];
#pragma unroll
    for (int i = 0; i < 2; i++)
#pragma unroll
        for (int j = 0; j < 8; j++)
#pragma unroll
            for (int t = 0; t < 4; t++) acc[i][j][t] = 0.f;

    const int lr = tid >> 1, lh = tid & 1;
    const size_t arow = (size_t)(m0 + lr) * C_ + lh * 32;
    const size_t brow = (size_t)(n0 + lr) * C_ + lh * 32;
    float irm = (task == 1) ? g_invrms[m0 + lr] : 1.f;
    float ba0 = 0.f, ba1 = 0.f, ba2 = 0.f, ba3 = 0.f;

    for (int c = 0; c < 4; c++) {
        const float* xrow = Afp + arow + c * 64;
        const uint4* pb  = (const uint4*)(Bh + brow + c * 64);
        const uint4* pbl = (const uint4*)(Bl + brow + c * 64);
        u32 sbase = (u32)lr * 128;
#pragma unroll
        for (int j = 0; j < 4; j++) {
            float4 f0 = *(const float4*)(xrow + j * 8);
            float4 f1 = *(const float4*)(xrow + j * 8 + 4);
            int colb = c * 64 + lh * 32 + j * 8;
            if (task == 1) {
                f0.x *= irm * s_g[colb];     f0.y *= irm * s_g[colb + 1];
                f0.z *= irm * s_g[colb + 2]; f0.w *= irm * s_g[colb + 3];
                f1.x *= irm * s_g[colb + 4]; f1.y *= irm * s_g[colb + 5];
                f1.z *= irm * s_g[colb + 6]; f1.w *= irm * s_g[colb + 7];
            } else if (doBeta) {
                const float* w0 = s_g + colb;
                ba0 += f0.x*w0[0]+f0.y*w0[1]+f0.z*w0[2]+f0.w*w0[3]+f1.x*w0[4]+f1.y*w0[5]+f1.z*w0[6]+f1.w*w0[7];
                const float* w1 = s_g + 256 + colb;
                ba1 += f0.x*w1[0]+f0.y*w1[1]+f0.z*w1[2]+f0.w*w1[3]+f1.x*w1[4]+f1.y*w1[5]+f1.z*w1[6]+f1.w*w1[7];
                const float* w2 = s_g + 512 + colb;
                ba2 += f0.x*w2[0]+f0.y*w2[1]+f0.z*w2[2]+f0.w*w2[3]+f1.x*w2[4]+f1.y*w2[5]+f1.z*w2[6]+f1.w*w2[7];
                const float* w3 = s_g + 768 + colb;
                ba3 += f0.x*w3[0]+f0.y*w3[1]+f0.z*w3[2]+f0.w*w3[3]+f1.x*w3[4]+f1.y*w3[5]+f1.z*w3[6]+f1.w*w3[7];
            }
            float r0, r1, d0, d1;
            u32 h0 = pack2(f0.x, f0.y, r0, r1); u32 l0 = pack2(r0, r1, d0, d1);
            u32 h1 = pack2(f0.z, f0.w, r0, r1); u32 l1 = pack2(r0, r1, d0, d1);
            u32 h2 = pack2(f1.x, f1.y, r0, r1); u32 l2 = pack2(r0, r1, d0, d1);
            u32 h3 = pack2(f1.z, f1.w, r0, r1); u32 l3 = pack2(r0, r1, d0, d1);
            u32 off = sbase + (u32)(((lh * 4 + j) ^ (lr & 7)) << 4);
            *(uint4*)(smem + OAH + off) = make_uint4(h0, h1, h2, h3);
            *(uint4*)(smem + OAL + off) = make_uint4(l0, l1, l2, l3);
            *(uint4*)(smem + OBH + off) = pb[j];
            *(uint4*)(smem + OBL + off) = pbl[j];
        }
        __syncthreads();
#pragma unroll
        for (int ks = 0; ks < 4; ks++) {
            u32 ah[2][4], al[2][4];
#pragma unroll
            for (int mm = 0; mm < 2; mm++) {
                int r = wm * 32 + mm * 16 + rA;
                u32 byt = (u32)r * 128 + (u32)((((2 * ks + cAx) ^ (r & 7)) << 4));
                ldmx4(ah[mm], sb + OAH + byt);
                ldmx4(al[mm], sb + OAL + byt);
            }
#pragma unroll
            for (int nh = 0; nh < 4; nh++) {
                int n = wn * 64 + nh * 16 + rB;
                u32 bytB = (u32)n * 128 + (u32)((((2 * ks + cBx) ^ (n & 7)) << 4));
                u32 bhf[4], blf[4];
                ldmx4(bhf, sb + OBH + bytB);
                ldmx4(blf, sb + OBL + bytB);
#pragma unroll
                for (int mm = 0; mm < 2; mm++) {
                    mma_bf16(acc[mm][nh * 2],     ah[mm], bhf[0], bhf[1]);
                    mma_bf16(acc[mm][nh * 2 + 1], ah[mm], bhf[2], bhf[3]);
                    mma_bf16(acc[mm][nh * 2],     al[mm], bhf[0], bhf[1]);
                    mma_bf16(acc[mm][nh * 2 + 1], al[mm], bhf[2], bhf[3]);
                    mma_bf16(acc[mm][nh * 2],     ah[mm], blf[0], blf[1]);
                    mma_bf16(acc[mm][nh * 2 + 1], ah[mm], blf[2], blf[3]);
                }
            }
        }
        __syncthreads();
    }

    if (doBeta) {
        ba0 += __shfl_xor_sync(0xffffffffu, ba0, 1);
        ba1 += __shfl_xor_sync(0xffffffffu, ba1, 1);
        ba2 += __shfl_xor_sync(0xffffffffu, ba2, 1);
        ba3 += __shfl_xor_sync(0xffffffffu, ba3, 1);
        if (lh == 0) {
            int m = m0 + lr, bb = m >> 12, n = m & (N_ - 1);
            g_beta[(bb * H_ + 0) * N_ + n] = 1.f / (1.f + expf(-ba0));
            g_beta[(bb * H_ + 1) * N_ + n] = 1.f / (1.f + expf(-ba1));
            g_beta[(bb * H_ + 2) * N_ + n] = 1.f / (1.f + expf(-ba2));
            g_beta[(bb * H_ + 3) * N_ + n] = 1.f / (1.f + expf(-ba3));
        }
    }

    // ---- epilogue ----
    const int qrow = lane >> 2, qcol = (lane & 3) * 2;
    if (mode <= 1) {
        __nv_bfloat16* Dh = (mode == 0) ? g_qh : g_kh;
        __nv_bfloat16* Dl = (mode == 0) ? g_ql : g_kl;
#pragma unroll
        for (int mm = 0; mm < 2; mm++) {
            float invl = 1.f, invh = 1.f;
            if (mode == 1) {
                float ssl = 0.f, ssh = 0.f;
#pragma unroll
                for (int nf = 0; nf < 8; nf++) {
                    float e0 = eluf(acc[mm][nf][0]); acc[mm][nf][0] = e0; ssl += e0 * e0;
                    float e1 = eluf(acc[mm][nf][1]); acc[mm][nf][1] = e1; ssl += e1 * e1;
                    float e2 = eluf(acc[mm][nf][2]); acc[mm][nf][2] = e2; ssh += e2 * e2;
                    float e3 = eluf(acc[mm][nf][3]); acc[mm][nf][3] = e3; ssh += e3 * e3;
                }
                ssl += __shfl_xor_sync(0xffffffffu, ssl, 1);
                ssl += __shfl_xor_sync(0xffffffffu, ssl, 2);
                ssh += __shfl_xor_sync(0xffffffffu, ssh, 1);
                ssh += __shfl_xor_sync(0xffffffffu, ssh, 2);
                invl = 1.f / (sqrtf(ssl) + 1e-6f);
                invh = 1.f / (sqrtf(ssh) + 1e-6f);
            }
            size_t r_lo = (size_t)(m0 + wm * 32 + mm * 16 + qrow);
            size_t r_hi = r_lo + 8;
#pragma unroll
            for (int nf = 0; nf < 8; nf++) {
                int cof = n0 + wn * 64 + nf * 8 + qcol;
                float v0 = acc[mm][nf][0] * invl, v1 = acc[mm][nf][1] * invl;
                float v2 = acc[mm][nf][2] * invh, v3 = acc[mm][nf][3] * invh;
                float r0, r1, d0, d1;
                u32 h01 = pack2(v0, v1, r0, r1); u32 l01 = pack2(r0, r1, d0, d1);
                u32 h23 = pack2(v2, v3, r0, r1); u32 l23 = pack2(r0, r1, d0, d1);
                *(u32*)(Dh + r_lo * C_ + cof) = h01;
                *(u32*)(Dl + r_lo * C_ + cof) = l01;
                *(u32*)(Dh + r_hi * C_ + cof) = h23;
                *(u32*)(Dl + r_hi * C_ + cof) = l23;
            }
        }
    } else {
        float* dst = (mode == 2) ? g_v : fout;
#pragma unroll
        for (int mm = 0; mm < 2; mm++) {
            size_t r_lo = (size_t)(m0 + wm * 32 + mm * 16 + qrow);
            size_t r_hi = r_lo + 8;
#pragma unroll
            for (int nf = 0; nf < 8; nf++) {
                int cof = n0 + wn * 64 + nf * 8 + qcol;
                *(float2*)(dst + r_lo * C_ + cof) = make_float2(acc[mm][nf][0], acc[mm][nf][1]);
                *(float2*)(dst + r_hi * C_ + cof) = make_float2(acc[mm][nf][2], acc[mm][nf][3]);
            }
        }
    }
}

// ---------------- K2: state apply + fused partials, 64-row tiles ----------------
// grid (64 bh, 64 ntiles). warps 0-3: y + per-row ss + k colsums; warps 4-7: pred + se partials.
__global__ void __launch_bounds__(256, 3)
state_mma_kernel(const float* __restrict__ S)
{
    extern __shared__ char smem[];
    const u32 sb = smem_u32(smem);
    const int tid = threadIdx.x, wid = tid >> 5, lane = tid & 31;
    const int bh = blockIdx.x, b = bh >> 2, h = bh & 3, nt = blockIdx.y;
    const int m0 = b * N_ + nt * 64;

    const u32 OQH = 0, OQL = 8192, OKH = 16384, OKL = 24576;
    const u32 OSH = 32768, OSL = 40960, ORED = 49152;

    // stage q/k split tiles [64 x 64]
    {
        const int lr = tid >> 2, qd = tid & 3;
        size_t gof = (size_t)(m0 + lr) * C_ + h * 64 + qd * 16;
        const uint4* pqh = (const uint4*)(g_qh + gof);
        const uint4* pql = (const uint4*)(g_ql + gof);
        const uint4* pkh = (const uint4*)(g_kh + gof);
        const uint4* pkl = (const uint4*)(g_kl + gof);
#pragma unroll
        for (int j = 0; j < 2; j++) {
            int cg = qd * 2 + j;
            u32 off = (u32)lr * 128 + (u32)((cg ^ (lr & 7)) << 4);
            *(uint4*)(smem + OQH + off) = pqh[j];
            *(uint4*)(smem + OQL + off) = pql[j];
            *(uint4*)(smem + OKH + off) = pkh[j];
            *(uint4*)(smem + OKL + off) = pkl[j];
        }
    }
    // Sd split tile [64 x 64]
    for (int t = tid; t < 4096; t += 256) {
        int i = t >> 6, j = t & 63;
        float v = S[(size_t)bh * 4096 + t] * 0.95f;
        __nv_bfloat16 hh = __float2bfloat16(v);
        __nv_bfloat16 ll = __float2bfloat16(v - __bfloat162float(hh));
        u32 byt = (u32)i * 128 + (u32)((((j >> 3) ^ (i & 7)) << 4)) + (u32)(j & 7) * 2;
        *(__nv_bfloat16*)(smem + OSH + byt) = hh;
        *(__nv_bfloat16*)(smem + OSL + byt) = ll;
    }
    __syncthreads();

    const int wm = wid & 3;
    const bool isPred = (wid >= 4);
    const u32 AH = isPred ? OKH : OQH, AL = isPred ? OKL : OQL;
    const int rA = (lane & 7) + ((lane >> 3) & 1) * 8, cAx = (lane >> 4) & 1;
    const int rB = (lane & 7) + ((lane >> 4) & 1) * 8, cBx = (lane >> 3) & 1;

    float acc[8][4];
#pragma unroll
    for (int j = 0; j < 8; j++)
#pragma unroll
        for (int t = 0; t < 4; t++) acc[j][t] = 0.f;

#pragma unroll
    for (int ks = 0; ks < 4; ks++) {
        u32 ah[4], al[4];
        int r = wm * 16 + rA;
        u32 byt = (u32)r * 128 + (u32)((((2 * ks + cAx) ^ (r & 7)) << 4));
        ldmx4(ah, sb + AH + byt);
        ldmx4(al, sb + AL + byt);
#pragma unroll
        for (int nh = 0; nh < 4; nh++) {
            int n = nh * 16 + rB;
            u32 bytB = (u32)n * 128 + (u32)((((2 * ks + cBx) ^ (n & 7)) << 4));
            u32 bhf[4], blf[4];
            ldmx4(bhf, sb + OSH + bytB);
            ldmx4(blf, sb + OSL + bytB);
            mma_bf16(acc[nh * 2],     ah, bhf[0], bhf[1]);
            mma_bf16(acc[nh * 2 + 1], ah, bhf[2], bhf[3]);
            mma_bf16(acc[nh * 2],     al, bhf[0], bhf[1]);
            mma_bf16(acc[nh * 2 + 1], al, bhf[2], bhf[3]);
            mma_bf16(acc[nh * 2],     ah, blf[0], blf[1]);
            mma_bf16(acc[nh * 2 + 1], ah, blf[2], blf[3]);
        }
    }

    const int qrow = lane >> 2, qcol = (lane & 3) * 2;
    if (!isPred) {
        // write y (fp32) + per-row ss
        size_t r_lo = (size_t)(m0 + wm * 16 + qrow);
        size_t r_hi = r_lo + 8;
        float ssl = 0.f, ssh = 0.f;
#pragma unroll
        for (int nf = 0; nf < 8; nf++) {
            int cof = h * 64 + nf * 8 + qcol;
            *(float2*)(g_y + r_lo * C_ + cof) = make_float2(acc[nf][0], acc[nf][1]);
            *(float2*)(g_y + r_hi * C_ + cof) = make_float2(acc[nf][2], acc[nf][3]);
            ssl += acc[nf][0] * acc[nf][0] + acc[nf][1] * acc[nf][1];
            ssh += acc[nf][2] * acc[nf][2] + acc[nf][3] * acc[nf][3];
        }
        ssl += __shfl_xor_sync(0xffffffffu, ssl, 1);
        ssl += __shfl_xor_sync(0xffffffffu, ssl, 2);
        ssh += __shfl_xor_sync(0xffffffffu, ssh, 1);
        ssh += __shfl_xor_sync(0xffffffffu, ssh, 2);
        if ((lane & 3) == 0) {
            g_ss[r_lo * H_ + h] = ssl;
            g_ss[r_hi * H_ + h] = ssh;
        }
        // k column sums over 64 rows (h + l)
        int col = wid * 16 + (lane & 15);
        int rbase = (lane >> 4) * 32;
        float sum = 0.f;
        for (int rr = 0; rr < 32; rr++) {
            int r = rbase + rr;
            u32 byt = (u32)r * 128 + (u32)((((col >> 3) ^ (r & 7)) << 4)) + (u32)(col & 7) * 2;
            sum += __bfloat162float(*(const __nv_bfloat16*)(smem + OKH + byt))
                 + __bfloat162float(*(const __nv_bfloat16*)(smem + OKL + byt));
        }
        sum += __shfl_xor_sync(0xffffffffu, sum, 16);
        if (lane < 16)
            g_pkey[((size_t)nt * 64 + bh) * 64 + wid * 16 + lane] = sum;
    } else {
        // se partials: sum over rows of beta*(v - pred)
        float sse0[8], sse1[8];
#pragma unroll
        for (int nf = 0; nf < 8; nf++) { sse0[nf] = 0.f; sse1[nf] = 0.f; }
        int rl = wm * 16 + qrow;
        float b_lo = g_beta[bh * N_ + nt * 64 + rl];
        float b_hi = g_beta[bh * N_ + nt * 64 + rl + 8];
        size_t glo = (size_t)(m0 + rl) * C_ + h * 64;
        size_t ghi = glo + 8 * C_;
#pragma unroll
        for (int nf = 0; nf < 8; nf++) {
            int cof = nf * 8 + qcol;
            float2 vlo = *(const float2*)(g_v + glo + cof);
            float2 vhi = *(const float2*)(g_v + ghi + cof);
            sse0[nf] += b_lo * (vlo.x - acc[nf][0]) + b_hi * (vhi.x - acc[nf][2]);
            sse1[nf] += b_lo * (vlo.y - acc[nf][1]) + b_hi * (vhi.y - acc[nf][3]);
        }
#pragma unroll
        for (int o = 4; o <= 16; o <<= 1) {
#pragma unroll
            for (int nf = 0; nf < 8; nf++) {
                sse0[nf] += __shfl_xor_sync(0xffffffffu, sse0[nf], o);
                sse1[nf] += __shfl_xor_sync(0xffffffffu, sse1[nf], o);
            }
        }
        if (lane < 4) {
            float* red = (float*)(smem + ORED) + (wid - 4) * 64;
#pragma unroll
            for (int nf = 0; nf < 8; nf++) {
                red[nf * 8 + lane * 2]     = sse0[nf];
                red[nf * 8 + lane * 2 + 1] = sse1[nf];
            }
        }
    }
    __syncthreads();
    if (tid < 64) {
        const float* red = (const float*)(smem + ORED);
        float se = red[tid] + red[64 + tid] + red[128 + tid] + red[192 + tid];
        g_perr[((size_t)nt * 64 + bh) * 64 + tid] = se;
    }
}

// ---------------- K3: inv rms per row ----------------
__global__ void __launch_bounds__(256)
invrms_kernel()
{
    int m = blockIdx.x * 256 + threadIdx.x;
    float4 s = *(const float4*)(g_ss + (size_t)m * 4);
    g_invrms[m] = rsqrtf((s.x + s.y + s.z + s.w) * (1.f / (float)C_) + 1e-6f);
}

// ---------------- K4: finalize means ----------------
__global__ void __launch_bounds__(256)
red_final_kernel()
{
    int gid = blockIdx.x * 256 + threadIdx.x;   // 0..4095
    int bh = gid >> 6, i = gid & 63;
    float se = 0.f, sk = 0.f;
#pragma unroll
    for (int c = 0; c < 64; c++) {
        se += g_perr[((size_t)c * 64 + bh) * 64 + i];
        sk += g_pkey[((size_t)c * 64 + bh) * 64 + i];
    }
    g_werr[gid] = se * (1.f / (float)N_);
    g_wkey[gid] = sk * (1.f / (float)N_);
}

// ---------------- K5: S_new ----------------
__global__ void __launch_bounds__(256)
snew_kernel(const float* __restrict__ S, float* __restrict__ out_s)
{
    int idx = blockIdx.x * 256 + threadIdx.x;
    int bh = idx >> 12;
    int i = (idx >> 6) & 63;
    int j = idx & 63;
    float val = S[idx] * 0.95f + g_werr[bh * 64 + i] * g_wkey[bh * 64 + j];
    out_s[idx] = fminf(fmaxf(val, -10.f), 10.f);
}

// ---------------- launcher ----------------
extern "C" void kernel_launch(void* const* d_in, const int* in_sizes, int n_in,
                              void* d_out, int out_size)
{
    const float* x    = (const float*)d_in[0];
    const float* S    = (const float*)d_in[1];
    const float* Wq   = (const float*)d_in[2];
    const float* Wk   = (const float*)d_in[3];
    const float* Wv   = (const float*)d_in[4];
    const float* Wb   = (const float*)d_in[5];
    const float* Wo   = (const float*)d_in[6];
    const float* grms = (const float*)d_in[7];
    float* out = (float*)d_out;

    static int init = 0;
    if (!init) {
        cudaFuncSetAttribute(gemm_mma_kernel, cudaFuncAttributeMaxDynamicSharedMemorySize, 65536);
        cudaFuncSetAttribute(state_mma_kernel, cudaFuncAttributeMaxDynamicSharedMemorySize, 50176);
        init = 1;
    }

    // weights -> split bf16
    convw_kernel<<<1024, 256>>>(Wq, Wk, Wv, Wo);

    // QKV projection from fp32 x (on-the-fly split) + fused beta
    gemm_mma_kernel<<<dim3(6, 512), 256, 65536>>>(0, x, Wb, grms, nullptr);

    // state apply: y, per-row ss, delta-rule partials (se, sk)
    state_mma_kernel<<<dim3(64, 64), 256, 50176>>>(S);

    // inv rms, finalize means, S_new
    invrms_kernel<<<M_ / 256, 256>>>();
    red_final_kernel<<<16, 256>>>();
    if (out_size >= OUT_MAIN + OUT_S) {
        snew_kernel<<<OUT_S / 256, 256>>>(S, out + OUT_MAIN);
    }

    // output projection from g_y (selected device-side) with fused rmsnorm -> d_out
    gemm_mma_kernel<<<dim3(2, 512), 256, 65536>>>(1, x, Wb, grms, out);
}

// round 6
// speedup vs baseline: 1.1483x; 1.1483x over previous
#include <cuda_runtime.h>
#include <cuda_bf16.h>
#include <math.h>

// ---------------- constants ----------------
#define B_ 16
#define N_ 4096
#define C_ 256
#define H_ 4
#define D_ 64
#define M_ (B_ * N_)              // 65536
#define OUT_MAIN (M_ * C_)        // 16777216
#define OUT_S (B_ * H_ * D_ * D_) // 262144

typedef unsigned int u32;
typedef unsigned long long u64;

// ---------------- device scratch ----------------
__device__ __nv_bfloat16 g_wph[B_ * C_ * C_], g_wpl[B_ * C_ * C_]; // W' = Sd@Wq per batch (split)
__device__ __nv_bfloat16 g_wsh[2][C_ * C_], g_wsl[2][C_ * C_];     // Wk, Wo (split)
__device__ float g_y[M_ * C_];
__device__ float g_beta[B_ * H_ * N_];
__device__ float g_ssp[M_ * 2];
__device__ float g_invrms[M_];
__device__ float g_mkp[512 * 256], g_mbkp[512 * 256];   // per-mtile k partials
__device__ float g_xbp[1024 * H_ * C_];                  // per-64row beta*x partials
__device__ float g_werr[64 * 64], g_wkey[64 * 64];

// ---------------- helpers ----------------
__device__ __forceinline__ u32 smem_u32(const void* p) {
    u32 a;
    asm("{ .reg .u64 t; cvta.to.shared.u64 t, %1; cvt.u32.u64 %0, t; }" : "=r"(a) : "l"(p));
    return a;
}
__device__ __forceinline__ void ldmx4(u32* r, u32 addr) {
    asm volatile("ldmatrix.sync.aligned.m8n8.x4.shared.b16 {%0,%1,%2,%3}, [%4];"
                 : "=r"(r[0]), "=r"(r[1]), "=r"(r[2]), "=r"(r[3]) : "r"(addr));
}
__device__ __forceinline__ void mma_bf16(float* d, const u32* a, u32 b0, u32 b1) {
    asm volatile("mma.sync.aligned.m16n8k16.row.col.f32.bf16.bf16.f32 "
                 "{%0,%1,%2,%3}, {%4,%5,%6,%7}, {%8,%9}, {%0,%1,%2,%3};"
                 : "+f"(d[0]), "+f"(d[1]), "+f"(d[2]), "+f"(d[3])
                 : "r"(a[0]), "r"(a[1]), "r"(a[2]), "r"(a[3]), "r"(b0), "r"(b1));
}
__device__ __forceinline__ u32 pack2(float a, float b, float& ra, float& rb) {
    __nv_bfloat16 h0 = __float2bfloat16(a), h1 = __float2bfloat16(b);
    ra = a - __bfloat162float(h0);
    rb = b - __bfloat162float(h1);
    return (u32)__bfloat16_as_ushort(h0) | ((u32)__bfloat16_as_ushort(h1) << 16);
}
__device__ __forceinline__ float eluf(float v) {
    return (v > 0.f) ? (v + 1.f) : expf(v);
}

// ---------------- K0: Wk, Wo -> split bf16 ----------------
__global__ void __launch_bounds__(256) convw_kernel(
    const float* __restrict__ Wk, const float* __restrict__ Wo)
{
    int gid = blockIdx.x * 256 + threadIdx.x;   // < 131072
    int sel = gid >> 16, idx = gid & 65535;
    const float* W = sel ? Wo : Wk;
    float v = W[idx];
    __nv_bfloat16 h = __float2bfloat16(v);
    g_wsh[sel][idx] = h;
    g_wsl[sel][idx] = __float2bfloat16(v - __bfloat162float(h));
}

// ---------------- K1: W'[b] = (0.95*S[b,h]) @ Wq_h, split bf16 ----------------
__global__ void __launch_bounds__(256)
wprime_kernel(const float* __restrict__ S, const float* __restrict__ Wq)
{
    extern __shared__ float sm[];        // sSdT[4096] + sWq[64*256] = 80KB
    float* sSdT = sm;                    // transposed: sSdT[j*64+i] = Sd[i][j]
    float* sWq = sm + 4096;
    int bh = blockIdx.x, b = bh >> 2, h = bh & 3, tid = threadIdx.x;
    for (int t = tid; t < 4096; t += 256) {
        int i = t >> 6, j = t & 63;
        sSdT[j * 64 + i] = S[(size_t)bh * 4096 + t] * 0.95f;
    }
    for (int t = tid; t < 64 * 256; t += 256)
        sWq[t] = Wq[(size_t)(h * 64 + (t >> 8)) * 256 + (t & 255)];
    __syncthreads();
    int i = tid & 63, stripe = tid >> 6;
#pragma unroll 1
    for (int cc = 0; cc < 64; cc++) {
        int c = stripe * 64 + cc;
        float acc = 0.f;
#pragma unroll
        for (int j = 0; j < 64; j++)
            acc += sSdT[j * 64 + i] * sWq[j * 256 + c];
        __nv_bfloat16 hh = __float2bfloat16(acc);
        size_t o = (size_t)b * 65536 + (size_t)(h * 64 + i) * 256 + c;
        g_wph[o] = hh;
        g_wpl[o] = __float2bfloat16(acc - __bfloat162float(hh));
    }
}

// ---------------- K2/K6: projection GEMM (split-bf16 from fp32 A) ----------------
// task 0: y = x @ W'[b]^T (grid 2 x 512), fused beta (bx==0) + per-row ss partials
// task 1: out = (y*invrms*grms) @ Wo^T (grid 2 x 512) -> fout
__global__ void __launch_bounds__(256, 2)
gemm_proj_kernel(int task, const float* __restrict__ Xfp,
                 const float* __restrict__ Wb, const float* __restrict__ grms,
                 float* __restrict__ fout)
{
    extern __shared__ char smem[];
    __shared__ float s_g[1024];
    __shared__ float sm_ss[128][2];
    const u32 sb = smem_u32(smem);
    const int tid = threadIdx.x, wid = tid >> 5, lane = tid & 31;
    const int m0 = blockIdx.y * 128;
    const int n0 = (int)blockIdx.x * 128;

    const float* Afp = (task == 0) ? Xfp : g_y;
    const __nv_bfloat16 *Bh, *Bl;
    bool doBeta = false;
    if (task == 0) {
        int b = m0 >> 12;
        Bh = g_wph + (size_t)b * 65536;
        Bl = g_wpl + (size_t)b * 65536;
        doBeta = (blockIdx.x == 0);
        if (doBeta) for (int i = tid; i < 1024; i += 256) s_g[i] = Wb[i];
    } else {
        Bh = g_wsh[1]; Bl = g_wsl[1];
        if (tid < 256) s_g[tid] = grms[tid];
    }
    __syncthreads();

    const u32 OAH = 0, OAL = 16384, OBH = 32768, OBL = 49152;
    const int wm = wid & 3, wn = wid >> 2;
    const int rA = (lane & 7) + ((lane >> 3) & 1) * 8, cAx = (lane >> 4) & 1;
    const int rB = (lane & 7) + ((lane >> 4) & 1) * 8, cBx = (lane >> 3) & 1;

    float acc[2][8][4];
#pragma unroll
    for (int i = 0; i < 2; i++)
#pragma unroll
        for (int j = 0; j < 8; j++)
#pragma unroll
            for (int t = 0; t < 4; t++) acc[i][j][t] = 0.f;

    const int lr = tid >> 1, lh = tid & 1;
    const size_t arow = (size_t)(m0 + lr) * C_ + lh * 32;
    const size_t brow = (size_t)(n0 + lr) * C_ + lh * 32;
    float irm = (task == 1) ? g_invrms[m0 + lr] : 1.f;
    float ba0 = 0.f, ba1 = 0.f, ba2 = 0.f, ba3 = 0.f;

    for (int c = 0; c < 4; c++) {
        const float* xrow = Afp + arow + c * 64;
        const uint4* pb  = (const uint4*)(Bh + brow + c * 64);
        const uint4* pbl = (const uint4*)(Bl + brow + c * 64);
        u32 sbase = (u32)lr * 128;
#pragma unroll
        for (int j = 0; j < 4; j++) {
            float4 f0 = *(const float4*)(xrow + j * 8);
            float4 f1 = *(const float4*)(xrow + j * 8 + 4);
            int colb = c * 64 + lh * 32 + j * 8;
            if (task == 1) {
                f0.x *= irm * s_g[colb];     f0.y *= irm * s_g[colb + 1];
                f0.z *= irm * s_g[colb + 2]; f0.w *= irm * s_g[colb + 3];
                f1.x *= irm * s_g[colb + 4]; f1.y *= irm * s_g[colb + 5];
                f1.z *= irm * s_g[colb + 6]; f1.w *= irm * s_g[colb + 7];
            } else if (doBeta) {
                const float* w0 = s_g + colb;
                ba0 += f0.x*w0[0]+f0.y*w0[1]+f0.z*w0[2]+f0.w*w0[3]+f1.x*w0[4]+f1.y*w0[5]+f1.z*w0[6]+f1.w*w0[7];
                const float* w1 = s_g + 256 + colb;
                ba1 += f0.x*w1[0]+f0.y*w1[1]+f0.z*w1[2]+f0.w*w1[3]+f1.x*w1[4]+f1.y*w1[5]+f1.z*w1[6]+f1.w*w1[7];
                const float* w2 = s_g + 512 + colb;
                ba2 += f0.x*w2[0]+f0.y*w2[1]+f0.z*w2[2]+f0.w*w2[3]+f1.x*w2[4]+f1.y*w2[5]+f1.z*w2[6]+f1.w*w2[7];
                const float* w3 = s_g + 768 + colb;
                ba3 += f0.x*w3[0]+f0.y*w3[1]+f0.z*w3[2]+f0.w*w3[3]+f1.x*w3[4]+f1.y*w3[5]+f1.z*w3[6]+f1.w*w3[7];
            }
            float r0, r1, d0, d1;
            u32 h0 = pack2(f0.x, f0.y, r0, r1); u32 l0 = pack2(r0, r1, d0, d1);
            u32 h1 = pack2(f0.z, f0.w, r0, r1); u32 l1 = pack2(r0, r1, d0, d1);
            u32 h2 = pack2(f1.x, f1.y, r0, r1); u32 l2 = pack2(r0, r1, d0, d1);
            u32 h3 = pack2(f1.z, f1.w, r0, r1); u32 l3 = pack2(r0, r1, d0, d1);
            u32 off = sbase + (u32)(((lh * 4 + j) ^ (lr & 7)) << 4);
            *(uint4*)(smem + OAH + off) = make_uint4(h0, h1, h2, h3);
            *(uint4*)(smem + OAL + off) = make_uint4(l0, l1, l2, l3);
            *(uint4*)(smem + OBH + off) = pb[j];
            *(uint4*)(smem + OBL + off) = pbl[j];
        }
        __syncthreads();
#pragma unroll
        for (int ks = 0; ks < 4; ks++) {
            u32 ah[2][4], al[2][4];
#pragma unroll
            for (int mm = 0; mm < 2; mm++) {
                int r = wm * 32 + mm * 16 + rA;
                u32 byt = (u32)r * 128 + (u32)((((2 * ks + cAx) ^ (r & 7)) << 4));
                ldmx4(ah[mm], sb + OAH + byt);
                ldmx4(al[mm], sb + OAL + byt);
            }
#pragma unroll
            for (int nh = 0; nh < 4; nh++) {
                int n = wn * 64 + nh * 16 + rB;
                u32 bytB = (u32)n * 128 + (u32)((((2 * ks + cBx) ^ (n & 7)) << 4));
                u32 bhf[4], blf[4];
                ldmx4(bhf, sb + OBH + bytB);
                ldmx4(blf, sb + OBL + bytB);
#pragma unroll
                for (int mm = 0; mm < 2; mm++) {
                    mma_bf16(acc[mm][nh * 2],     ah[mm], bhf[0], bhf[1]);
                    mma_bf16(acc[mm][nh * 2 + 1], ah[mm], bhf[2], bhf[3]);
                    mma_bf16(acc[mm][nh * 2],     al[mm], bhf[0], bhf[1]);
                    mma_bf16(acc[mm][nh * 2 + 1], al[mm], bhf[2], bhf[3]);
                    mma_bf16(acc[mm][nh * 2],     ah[mm], blf[0], blf[1]);
                    mma_bf16(acc[mm][nh * 2 + 1], ah[mm], blf[2], blf[3]);
                }
            }
        }
        __syncthreads();
    }

    if (doBeta) {
        ba0 += __shfl_xor_sync(0xffffffffu, ba0, 1);
        ba1 += __shfl_xor_sync(0xffffffffu, ba1, 1);
        ba2 += __shfl_xor_sync(0xffffffffu, ba2, 1);
        ba3 += __shfl_xor_sync(0xffffffffu, ba3, 1);
        if (lh == 0) {
            int m = m0 + lr, bb = m >> 12, n = m & (N_ - 1);
            g_beta[(bb * H_ + 0) * N_ + n] = 1.f / (1.f + expf(-ba0));
            g_beta[(bb * H_ + 1) * N_ + n] = 1.f / (1.f + expf(-ba1));
            g_beta[(bb * H_ + 2) * N_ + n] = 1.f / (1.f + expf(-ba2));
            g_beta[(bb * H_ + 3) * N_ + n] = 1.f / (1.f + expf(-ba3));
        }
    }

    // ---- epilogue ----
    const int qrow = lane >> 2, qcol = (lane & 3) * 2;
    if (task == 0) {
        // write y + per-row ss partial (this block's 128 cols)
#pragma unroll
        for (int mm = 0; mm < 2; mm++) {
            size_t r_lo = (size_t)(m0 + wm * 32 + mm * 16 + qrow);
            size_t r_hi = r_lo + 8;
            float ssl = 0.f, ssh = 0.f;
#pragma unroll
            for (int nf = 0; nf < 8; nf++) {
                int cof = n0 + wn * 64 + nf * 8 + qcol;
                *(float2*)(g_y + r_lo * C_ + cof) = make_float2(acc[mm][nf][0], acc[mm][nf][1]);
                *(float2*)(g_y + r_hi * C_ + cof) = make_float2(acc[mm][nf][2], acc[mm][nf][3]);
                ssl += acc[mm][nf][0] * acc[mm][nf][0] + acc[mm][nf][1] * acc[mm][nf][1];
                ssh += acc[mm][nf][2] * acc[mm][nf][2] + acc[mm][nf][3] * acc[mm][nf][3];
            }
            ssl += __shfl_xor_sync(0xffffffffu, ssl, 1);
            ssl += __shfl_xor_sync(0xffffffffu, ssl, 2);
            ssh += __shfl_xor_sync(0xffffffffu, ssh, 1);
            ssh += __shfl_xor_sync(0xffffffffu, ssh, 2);
            if ((lane & 3) == 0) {
                sm_ss[wm * 32 + mm * 16 + qrow][wn]     = ssl;
                sm_ss[wm * 32 + mm * 16 + qrow + 8][wn] = ssh;
            }
        }
        __syncthreads();
        if (tid < 128)
            g_ssp[(size_t)(m0 + tid) * 2 + (n0 >> 7)] = sm_ss[tid][0] + sm_ss[tid][1];
    } else {
#pragma unroll
        for (int mm = 0; mm < 2; mm++) {
            size_t r_lo = (size_t)(m0 + wm * 32 + mm * 16 + qrow);
            size_t r_hi = r_lo + 8;
#pragma unroll
            for (int nf = 0; nf < 8; nf++) {
                int cof = n0 + wn * 64 + nf * 8 + qcol;
                *(float2*)(fout + r_lo * C_ + cof) = make_float2(acc[mm][nf][0], acc[mm][nf][1]);
                *(float2*)(fout + r_hi * C_ + cof) = make_float2(acc[mm][nf][2], acc[mm][nf][3]);
            }
        }
    }
}

// ---------------- K4: k GEMM + fused elu/L2norm + mk/mbk reductions ----------------
// grid (2, 512). k never stored; only per-mtile partial sums emitted.
__global__ void __launch_bounds__(256, 2)
gemm_k_kernel(const float* __restrict__ Xfp)
{
    extern __shared__ char smem[];
    const u32 sb = smem_u32(smem);
    const int tid = threadIdx.x, wid = tid >> 5, lane = tid & 31;
    const int m0 = blockIdx.y * 128;
    const int n0 = (int)blockIdx.x * 128;
    const __nv_bfloat16* Bh = g_wsh[0];
    const __nv_bfloat16* Bl = g_wsl[0];

    const u32 OAH = 0, OAL = 16384, OBH = 32768, OBL = 49152;
    const int wm = wid & 3, wn = wid >> 2;
    const int rA = (lane & 7) + ((lane >> 3) & 1) * 8, cAx = (lane >> 4) & 1;
    const int rB = (lane & 7) + ((lane >> 4) & 1) * 8, cBx = (lane >> 3) & 1;

    float acc[2][8][4];
#pragma unroll
    for (int i = 0; i < 2; i++)
#pragma unroll
        for (int j = 0; j < 8; j++)
#pragma unroll
            for (int t = 0; t < 4; t++) acc[i][j][t] = 0.f;

    const int lr = tid >> 1, lh = tid & 1;
    const size_t arow = (size_t)(m0 + lr) * C_ + lh * 32;
    const size_t brow = (size_t)(n0 + lr) * C_ + lh * 32;

    for (int c = 0; c < 4; c++) {
        const float* xrow = Xfp + arow + c * 64;
        const uint4* pb  = (const uint4*)(Bh + brow + c * 64);
        const uint4* pbl = (const uint4*)(Bl + brow + c * 64);
        u32 sbase = (u32)lr * 128;
#pragma unroll
        for (int j = 0; j < 4; j++) {
            float4 f0 = *(const float4*)(xrow + j * 8);
            float4 f1 = *(const float4*)(xrow + j * 8 + 4);
            float r0, r1, d0, d1;
            u32 h0 = pack2(f0.x, f0.y, r0, r1); u32 l0 = pack2(r0, r1, d0, d1);
            u32 h1 = pack2(f0.z, f0.w, r0, r1); u32 l1 = pack2(r0, r1, d0, d1);
            u32 h2 = pack2(f1.x, f1.y, r0, r1); u32 l2 = pack2(r0, r1, d0, d1);
            u32 h3 = pack2(f1.z, f1.w, r0, r1); u32 l3 = pack2(r0, r1, d0, d1);
            u32 off = sbase + (u32)(((lh * 4 + j) ^ (lr & 7)) << 4);
            *(uint4*)(smem + OAH + off) = make_uint4(h0, h1, h2, h3);
            *(uint4*)(smem + OAL + off) = make_uint4(l0, l1, l2, l3);
            *(uint4*)(smem + OBH + off) = pb[j];
            *(uint4*)(smem + OBL + off) = pbl[j];
        }
        __syncthreads();
#pragma unroll
        for (int ks = 0; ks < 4; ks++) {
            u32 ah[2][4], al[2][4];
#pragma unroll
            for (int mm = 0; mm < 2; mm++) {
                int r = wm * 32 + mm * 16 + rA;
                u32 byt = (u32)r * 128 + (u32)((((2 * ks + cAx) ^ (r & 7)) << 4));
                ldmx4(ah[mm], sb + OAH + byt);
                ldmx4(al[mm], sb + OAL + byt);
            }
#pragma unroll
            for (int nh = 0; nh < 4; nh++) {
                int n = wn * 64 + nh * 16 + rB;
                u32 bytB = (u32)n * 128 + (u32)((((2 * ks + cBx) ^ (n & 7)) << 4));
                u32 bhf[4], blf[4];
                ldmx4(bhf, sb + OBH + bytB);
                ldmx4(blf, sb + OBL + bytB);
#pragma unroll
                for (int mm = 0; mm < 2; mm++) {
                    mma_bf16(acc[mm][nh * 2],     ah[mm], bhf[0], bhf[1]);
                    mma_bf16(acc[mm][nh * 2 + 1], ah[mm], bhf[2], bhf[3]);
                    mma_bf16(acc[mm][nh * 2],     al[mm], bhf[0], bhf[1]);
                    mma_bf16(acc[mm][nh * 2 + 1], al[mm], bhf[2], bhf[3]);
                    mma_bf16(acc[mm][nh * 2],     ah[mm], blf[0], blf[1]);
                    mma_bf16(acc[mm][nh * 2 + 1], ah[mm], blf[2], blf[3]);
                }
            }
        }
        __syncthreads();
    }

    // ---- epilogue: elu+1, per-head L2 norm, reduce mk & beta-weighted mbk over rows ----
    const int qrow = lane >> 2, qcol = (lane & 3) * 2;
    const int head = (n0 >> 6) + wn;                 // global head of this warp
    const int bhh = (m0 >> 12) * H_ + head;
    float mk0[8], mk1[8], mbk0[8], mbk1[8];
#pragma unroll
    for (int nf = 0; nf < 8; nf++) { mk0[nf] = mk1[nf] = mbk0[nf] = mbk1[nf] = 0.f; }

#pragma unroll
    for (int mm = 0; mm < 2; mm++) {
        float ssl = 0.f, ssh = 0.f;
#pragma unroll
        for (int nf = 0; nf < 8; nf++) {
            float e0 = eluf(acc[mm][nf][0]); acc[mm][nf][0] = e0; ssl += e0 * e0;
            float e1 = eluf(acc[mm][nf][1]); acc[mm][nf][1] = e1; ssl += e1 * e1;
            float e2 = eluf(acc[mm][nf][2]); acc[mm][nf][2] = e2; ssh += e2 * e2;
            float e3 = eluf(acc[mm][nf][3]); acc[mm][nf][3] = e3; ssh += e3 * e3;
        }
        ssl += __shfl_xor_sync(0xffffffffu, ssl, 1);
        ssl += __shfl_xor_sync(0xffffffffu, ssl, 2);
        ssh += __shfl_xor_sync(0xffffffffu, ssh, 1);
        ssh += __shfl_xor_sync(0xffffffffu, ssh, 2);
        float invl = 1.f / (sqrtf(ssl) + 1e-6f);
        float invh = 1.f / (sqrtf(ssh) + 1e-6f);
        int nrow = (m0 & (N_ - 1)) + wm * 32 + mm * 16 + qrow;
        float b_lo = g_beta[bhh * N_ + nrow];
        float b_hi = g_beta[bhh * N_ + nrow + 8];
#pragma unroll
        for (int nf = 0; nf < 8; nf++) {
            float v0 = acc[mm][nf][0] * invl, v1 = acc[mm][nf][1] * invl;
            float v2 = acc[mm][nf][2] * invh, v3 = acc[mm][nf][3] * invh;
            mk0[nf]  += v0 + v2;
            mk1[nf]  += v1 + v3;
            mbk0[nf] += b_lo * v0 + b_hi * v2;
            mbk1[nf] += b_lo * v1 + b_hi * v3;
        }
    }
#pragma unroll
    for (int o = 4; o <= 16; o <<= 1) {
#pragma unroll
        for (int nf = 0; nf < 8; nf++) {
            mk0[nf]  += __shfl_xor_sync(0xffffffffu, mk0[nf], o);
            mk1[nf]  += __shfl_xor_sync(0xffffffffu, mk1[nf], o);
            mbk0[nf] += __shfl_xor_sync(0xffffffffu, mbk0[nf], o);
            mbk1[nf] += __shfl_xor_sync(0xffffffffu, mbk1[nf], o);
        }
    }
    float* red = (float*)smem;   // reuse staging smem: [0,512) mk, [512,1024) mbk
    if (lane < 4) {
#pragma unroll
        for (int nf = 0; nf < 8; nf++) {
            red[wid * 64 + nf * 8 + lane * 2]           = mk0[nf];
            red[wid * 64 + nf * 8 + lane * 2 + 1]       = mk1[nf];
            red[512 + wid * 64 + nf * 8 + lane * 2]     = mbk0[nf];
            red[512 + wid * 64 + nf * 8 + lane * 2 + 1] = mbk1[nf];
        }
    }
    __syncthreads();
    if (tid < 128) {
        int hh = tid >> 6, col = tid & 63;
        float s = red[(hh * 4 + 0) * 64 + col] + red[(hh * 4 + 1) * 64 + col]
                + red[(hh * 4 + 2) * 64 + col] + red[(hh * 4 + 3) * 64 + col];
        g_mkp[(size_t)blockIdx.y * 256 + n0 + hh * 64 + col] = s;
    } else {
        int t2 = tid - 128, hh = t2 >> 6, col = t2 & 63;
        float s = red[512 + (hh * 4 + 0) * 64 + col] + red[512 + (hh * 4 + 1) * 64 + col]
                + red[512 + (hh * 4 + 2) * 64 + col] + red[512 + (hh * 4 + 3) * 64 + col];
        g_mbkp[(size_t)blockIdx.y * 256 + n0 + hh * 64 + col] = s;
    }
}

// ---------------- K3: xbar partials = sum_n beta*x over 64-row chunks ----------------
__global__ void __launch_bounds__(256)
xbar_kernel(const float* __restrict__ x)
{
    __shared__ float sbeta[64][4];
    int blk = blockIdx.x, m0 = blk * 64, tid = threadIdx.x;
    {
        int r = tid >> 2, h = tid & 3;
        int m = m0 + r, b = m >> 12, n = m & (N_ - 1);
        sbeta[r][h] = g_beta[(b * H_ + h) * N_ + n];
    }
    __syncthreads();
    float a0 = 0.f, a1 = 0.f, a2 = 0.f, a3 = 0.f;
    for (int r = 0; r < 64; r++) {
        float xv = x[(size_t)(m0 + r) * C_ + tid];
        a0 += xv * sbeta[r][0];
        a1 += xv * sbeta[r][1];
        a2 += xv * sbeta[r][2];
        a3 += xv * sbeta[r][3];
    }
    g_xbp[((size_t)blk * 4 + 0) * 256 + tid] = a0;
    g_xbp[((size_t)blk * 4 + 1) * 256 + tid] = a1;
    g_xbp[((size_t)blk * 4 + 2) * 256 + tid] = a2;
    g_xbp[((size_t)blk * 4 + 3) * 256 + tid] = a3;
}

// ---------------- K5a: invrms ----------------
__global__ void __launch_bounds__(256)
invrms_kernel()
{
    int m = blockIdx.x * 256 + threadIdx.x;
    float s = g_ssp[(size_t)m * 2] + g_ssp[(size_t)m * 2 + 1];
    g_invrms[m] = rsqrtf(s * (1.f / (float)C_) + 1e-6f);
}

// ---------------- K5b: finalize werr/wkey ----------------
// w_err = Wv@xbar - Sd@mbk ; wkey = mk
__global__ void __launch_bounds__(256)
final_kernel(const float* __restrict__ S, const float* __restrict__ Wv)
{
    __shared__ float s_mk[64], s_mbk[64], s_xbar[256];
    int bh = blockIdx.x, b = bh >> 2, h = bh & 3, tid = threadIdx.x;
    {
        float a = 0.f;
        for (int t = 0; t < 64; t++)
            a += g_xbp[((size_t)(b * 64 + t) * 4 + h) * 256 + tid];
        s_xbar[tid] = a * (1.f / (float)N_);
    }
    if (tid < 64) {
        float s = 0.f;
        for (int t = 0; t < 32; t++)
            s += g_mkp[(size_t)(b * 32 + t) * 256 + h * 64 + tid];
        s_mk[tid] = s * (1.f / (float)N_);
    } else if (tid < 128) {
        int c = tid - 64;
        float s = 0.f;
        for (int t = 0; t < 32; t++)
            s += g_mbkp[(size_t)(b * 32 + t) * 256 + h * 64 + c];
        s_mbk[c] = s * (1.f / (float)N_);
    }
    __syncthreads();
    if (tid < 64) {
        int i = tid;
        const float* wv = Wv + (size_t)(h * 64 + i) * 256;
        float mbv = 0.f;
        for (int c = 0; c < 256; c++) mbv += wv[c] * s_xbar[c];
        const float* sd = S + (size_t)bh * 4096 + (size_t)i * 64;
        float sp = 0.f;
        for (int j = 0; j < 64; j++) sp += 0.95f * sd[j] * s_mbk[j];
        g_werr[bh * 64 + i] = mbv - sp;
        g_wkey[bh * 64 + i] = s_mk[i];
    }
}

// ---------------- K5c: S_new ----------------
__global__ void __launch_bounds__(256)
snew_kernel(const float* __restrict__ S, float* __restrict__ out_s)
{
    int idx = blockIdx.x * 256 + threadIdx.x;
    int bh = idx >> 12;
    int i = (idx >> 6) & 63;
    int j = idx & 63;
    float val = S[idx] * 0.95f + g_werr[bh * 64 + i] * g_wkey[bh * 64 + j];
    out_s[idx] = fminf(fmaxf(val, -10.f), 10.f);
}

// ---------------- launcher ----------------
extern "C" void kernel_launch(void* const* d_in, const int* in_sizes, int n_in,
                              void* d_out, int out_size)
{
    const float* x    = (const float*)d_in[0];
    const float* S    = (const float*)d_in[1];
    const float* Wq   = (const float*)d_in[2];
    const float* Wk   = (const float*)d_in[3];
    const float* Wv   = (const float*)d_in[4];
    const float* Wb   = (const float*)d_in[5];
    const float* Wo   = (const float*)d_in[6];
    const float* grms = (const float*)d_in[7];
    float* out = (float*)d_out;

    static int init = 0;
    if (!init) {
        cudaFuncSetAttribute(gemm_proj_kernel, cudaFuncAttributeMaxDynamicSharedMemorySize, 65536);
        cudaFuncSetAttribute(gemm_k_kernel, cudaFuncAttributeMaxDynamicSharedMemorySize, 65536);
        cudaFuncSetAttribute(wprime_kernel, cudaFuncAttributeMaxDynamicSharedMemorySize, 81920);
        init = 1;
    }

    // Wk/Wo splits; W' = Sd@Wq per batch
    convw_kernel<<<512, 256>>>(Wk, Wo);
    wprime_kernel<<<64, 256, 81920>>>(S, Wq);

    // y = x @ W'^T (+ beta, + ss partials)
    gemm_proj_kernel<<<dim3(2, 512), 256, 65536>>>(0, x, Wb, grms, nullptr);

    // xbar partials (needs beta)
    xbar_kernel<<<1024, 256>>>(x);

    // k GEMM + fused reductions (needs beta)
    gemm_k_kernel<<<dim3(2, 512), 256, 65536>>>(x);

    // invrms, werr/wkey, S_new
    invrms_kernel<<<M_ / 256, 256>>>();
    final_kernel<<<64, 256>>>(S, Wv);
    if (out_size >= OUT_MAIN + OUT_S) {
        snew_kernel<<<OUT_S / 256, 256>>>(S, out + OUT_MAIN);
    }

    // out = (y * invrms * grms) @ Wo^T
    gemm_proj_kernel<<<dim3(2, 512), 256, 65536>>>(1, x, Wb, grms, out);
}